// round 11
// baseline (speedup 1.0000x reference)
#include <cuda_runtime.h>
#include <math.h>
#include <stdint.h>

// Problem: B=2, N=1024, T=12, H=64, F=1
#define NB 1024
#define IMP_OFF  0
#define PRED_OFF 24576
#define REP_OFF  49152

// ---------------- persistent scratch (device globals; no runtime allocation) ------
__device__ __align__(16) float g_h   [2*64*NB];
__device__ __align__(16) float g_E64 [4*64*NB];
__device__ __align__(16) float g_F64 [4*64*NB];
__device__ __align__(16) float g_G64 [4*64*NB];
__device__ __align__(16) float g_H64 [4*64*NB];
__device__ __align__(16) float g_Dx  [4*2*NB];
__device__ __align__(16) float g_Ex  [4*2*NB];
__device__ __align__(16) float g_Fx  [4*2*NB];
__device__ __align__(16) float g_u   [2*64*NB];
__device__ __align__(16) float g_rh  [2*64*NB];
__device__ __align__(16) float g_z1  [2*2*NB];
__device__ __align__(16) float g_z2  [2*2*NB];
__device__ __align__(16) float g_rs  [4*NB];
__device__ __align__(16) float g_rep [12*2*128*NB];
// tf32 hi/lo split of adjacency (precomputed once per replay)
__device__ __align__(16) uint32_t g_Ah[4*1024*1024];
__device__ __align__(16) uint32_t g_Al[4*1024*1024];
// transposed weights [k][c]
__device__ __align__(16) float g_Wlout_t[128*64];
__device__ __align__(16) float g_Wr_t   [330*64];
__device__ __align__(16) float g_Wu_t   [330*64];
__device__ __align__(16) float g_Wc_t   [330*64];
__device__ __align__(16) float g_M_t    [2*66*64];
__device__ __align__(16) float g_vb     [2*64];

// ---------------- helpers ----------------------------------------------------------
__device__ __forceinline__ void tf32_split1(float x, uint32_t& h, uint32_t& l) {
    asm("cvt.rna.tf32.f32 %0, %1;" : "=r"(h) : "f"(x));
    float r = x - __uint_as_float(h);
    asm("cvt.rna.tf32.f32 %0, %1;" : "=r"(l) : "f"(r));
}
#define MMA_TF32(d, a, b) \
    asm volatile("mma.sync.aligned.m16n8k8.row.col.f32.tf32.tf32.f32 " \
        "{%0,%1,%2,%3}, {%4,%5,%6,%7}, {%8,%9}, {%0,%1,%2,%3};" \
        : "+f"((d)[0]), "+f"((d)[1]), "+f"((d)[2]), "+f"((d)[3]) \
        : "r"((a)[0]), "r"((a)[1]), "r"((a)[2]), "r"((a)[3]), \
          "r"((b)[0]), "r"((b)[1]))

__global__ void init_h_kernel()
{
    int i = blockIdx.x * 256 + threadIdx.x;
    if (i < 2*64*NB) g_h[i] = 0.f;
}

__global__ void prep_adjsplit_kernel(const float* __restrict__ adj)
{
    size_t i = (size_t)blockIdx.x * 256 + threadIdx.x;
    float a = adj[i];
    uint32_t h, l;
    tf32_split1(a, h, l);
    g_Ah[i] = h;
    g_Al[i] = l;
}

__global__ void prep_weights_kernel(const float* __restrict__ Wr,
                                    const float* __restrict__ Wu,
                                    const float* __restrict__ Wc,
                                    const float* __restrict__ Wlout)
{
    int idx = blockIdx.x * 256 + threadIdx.x;
    if (idx >= 330*64) return;
    int j = idx >> 6;
    int i = idx & 63;
    g_Wr_t[idx] = Wr[i*330 + j];
    g_Wu_t[idx] = Wu[i*330 + j];
    g_Wc_t[idx] = Wc[i*330 + j];
    if (j < 128) g_Wlout_t[idx] = Wlout[i*128 + j];
}

__global__ void prep_M_kernel(const float* __restrict__ Wgc,
                              const float* __restrict__ Wdin,
                              const float* __restrict__ bdin)
{
    const int s = blockIdx.y;
    int idx = blockIdx.x * 256 + threadIdx.x;
    if (idx < 66*64) {
        int j = idx >> 6, c = idx & 63;
        float acc = 0.f;
        for (int k = 0; k < 64; k++)
            acc += Wgc[c*128 + s*64 + k] * Wdin[k*66 + j];
        g_M_t[s*66*64 + idx] = acc;
    } else if (idx < 66*64 + 64) {
        int c = idx - 66*64;
        float acc = 0.f;
        for (int k = 0; k < 64; k++)
            acc += Wgc[c*128 + s*64 + k] * bdin[k];
        g_vb[s*64 + c] = acc;
    }
}

__global__ __launch_bounds__(256) void rowsum_kernel(const float* __restrict__ adj)
{
    const int sb = blockIdx.y;
    const int warp = threadIdx.x >> 5, lane = threadIdx.x & 31;
    const int w = blockIdx.x * 8 + warp;
    const float* Arow = adj + (size_t)sb*1048576 + (size_t)w*1024;
    float a = 0.f;
    #pragma unroll
    for (int j = 0; j < 8; j++) {
        float4 av = *(const float4*)&Arow[lane*4 + j*128];
        a += av.x + av.y + av.z + av.w;
    }
    #pragma unroll
    for (int off = 16; off; off >>= 1) a += __shfl_down_sync(0xffffffffu, a, off);
    if (lane == 0) g_rs[sb*1024 + w] = a;
}

// =====================================================================================
// Tensor-pipe diffusion via warp mma.sync (tf32, 3-term hi/lo split — ~2^-22 exact):
//   O[sb][c][w] = sum_v Z[c][v] * A[sb][w][v]
// CTA: M=64(all c) x N=64(w), 256 thr (8 warps = 2 m-split x 4 n-split; warp M32xN16).
// grid (16, 4). K=1024 as 128 k8-steps; fragments loaded directly from L2.
// stage 0: h->E  1: E->F  2: rh->G  3: G->H
// =====================================================================================
__global__ __launch_bounds__(256) void diffuse_mma_kernel(int stage)
{
    const int sb = blockIdx.y;
    const float* Z; float* O;
    switch (stage) {
        case 0:  Z = g_h   + (sb&1)*65536; O = g_E64 + sb*65536; break;
        case 1:  Z = g_E64 + sb*65536;     O = g_F64 + sb*65536; break;
        case 2:  Z = g_rh  + (sb&1)*65536; O = g_G64 + sb*65536; break;
        default: Z = g_G64 + sb*65536;     O = g_H64 + sb*65536; break;
    }
    const uint32_t* Ah = g_Ah + (size_t)sb*1048576;
    const uint32_t* Al = g_Al + (size_t)sb*1048576;

    const int tid  = threadIdx.x;
    const int wid  = tid >> 5, lane = tid & 31;
    const int wm   = wid >> 2;          // 0..1  -> m_base 0/32
    const int wn   = wid & 3;           // 0..3  -> 16-wide n slice
    const int gid  = lane >> 2;         // 0..7
    const int tig  = lane & 3;          // 0..3
    const int m_base = wm * 32;
    const int n_base = blockIdx.x * 64 + wn * 16;

    // per-thread row pointers
    const float* Zr0 = Z + (size_t)(m_base + gid)*1024      + tig;   // mt=0, a0/a2
    const float* Zr1 = Z + (size_t)(m_base + gid + 8)*1024  + tig;   // mt=0, a1/a3
    const float* Zr2 = Z + (size_t)(m_base + 16 + gid)*1024 + tig;   // mt=1
    const float* Zr3 = Z + (size_t)(m_base + 24 + gid)*1024 + tig;
    const uint32_t* Bh0 = Ah + (size_t)(n_base + gid)*1024     + tig; // nt=0
    const uint32_t* Bh1 = Ah + (size_t)(n_base + 8 + gid)*1024 + tig; // nt=1
    const uint32_t* Bl0 = Al + (size_t)(n_base + gid)*1024     + tig;
    const uint32_t* Bl1 = Al + (size_t)(n_base + 8 + gid)*1024 + tig;

    float acc[2][2][4] = {};

    for (int kt = 0; kt < 128; kt++) {
        const int k0 = kt * 8;
        // A fragments (Z), hi/lo from one load each
        uint32_t zh[2][4], zl[2][4];
        {
            float z00 = __ldg(Zr0 + k0),     z01 = __ldg(Zr1 + k0);
            float z02 = __ldg(Zr0 + k0 + 4), z03 = __ldg(Zr1 + k0 + 4);
            float z10 = __ldg(Zr2 + k0),     z11 = __ldg(Zr3 + k0);
            float z12 = __ldg(Zr2 + k0 + 4), z13 = __ldg(Zr3 + k0 + 4);
            tf32_split1(z00, zh[0][0], zl[0][0]);
            tf32_split1(z01, zh[0][1], zl[0][1]);
            tf32_split1(z02, zh[0][2], zl[0][2]);
            tf32_split1(z03, zh[0][3], zl[0][3]);
            tf32_split1(z10, zh[1][0], zl[1][0]);
            tf32_split1(z11, zh[1][1], zl[1][1]);
            tf32_split1(z12, zh[1][2], zl[1][2]);
            tf32_split1(z13, zh[1][3], zl[1][3]);
        }
        // B fragments (adjacency splits)
        uint32_t bh[2][2], bl[2][2];
        bh[0][0] = __ldg(Bh0 + k0); bh[0][1] = __ldg(Bh0 + k0 + 4);
        bh[1][0] = __ldg(Bh1 + k0); bh[1][1] = __ldg(Bh1 + k0 + 4);
        bl[0][0] = __ldg(Bl0 + k0); bl[0][1] = __ldg(Bl0 + k0 + 4);
        bl[1][0] = __ldg(Bl1 + k0); bl[1][1] = __ldg(Bl1 + k0 + 4);

        #pragma unroll
        for (int mt = 0; mt < 2; mt++)
            #pragma unroll
            for (int nt = 0; nt < 2; nt++) {
                MMA_TF32(acc[mt][nt], zh[mt], bh[nt]);
                MMA_TF32(acc[mt][nt], zh[mt], bl[nt]);
                MMA_TF32(acc[mt][nt], zl[mt], bh[nt]);
            }
    }

    // epilogue: direct scatter stores
    #pragma unroll
    for (int mt = 0; mt < 2; mt++) {
        #pragma unroll
        for (int nt = 0; nt < 2; nt++) {
            const int c0 = m_base + mt*16 + gid;
            const int w  = n_base + nt*8 + 2*tig;
            O[(size_t)c0*1024 + w]       = acc[mt][nt][0];
            O[(size_t)c0*1024 + w + 1]   = acc[mt][nt][1];
            O[(size_t)(c0+8)*1024 + w]   = acc[mt][nt][2];
            O[(size_t)(c0+8)*1024 + w+1] = acc[mt][nt][3];
        }
    }
}

// =====================================================================================
// 2-channel diffusion. stage 0: z1->Dx  1: z2->Ex  2: Ex->Fx
// =====================================================================================
__global__ __launch_bounds__(256) void diffuse2_kernel(const float* __restrict__ adj, int stage)
{
    const int sb = blockIdx.y;
    __shared__ float zs[2][NB];
    const float* src;
    if      (stage == 0) src = g_z1 + (sb&1)*2048;
    else if (stage == 1) src = g_z2 + (sb&1)*2048;
    else                 src = g_Ex + sb*2048;
    for (int i = threadIdx.x; i < 2048; i += 256) zs[i >> 10][i & 1023] = src[i];
    __syncthreads();

    const int warp = threadIdx.x >> 5, lane = threadIdx.x & 31;
    const int w = blockIdx.x * 8 + warp;
    const float* Arow = adj + (size_t)sb*1048576 + (size_t)w*1024;
    float a0 = 0.f, a1 = 0.f;
    #pragma unroll
    for (int j = 0; j < 8; j++) {
        const int v = lane*4 + j*128;
        float4 av = *(const float4*)&Arow[v];
        float4 z0 = *(const float4*)&zs[0][v];
        float4 z1 = *(const float4*)&zs[1][v];
        a0 += av.x*z0.x + av.y*z0.y + av.z*z0.z + av.w*z0.w;
        a1 += av.x*z1.x + av.y*z1.y + av.z*z1.z + av.w*z1.w;
    }
    #pragma unroll
    for (int off = 16; off; off >>= 1) {
        a0 += __shfl_down_sync(0xffffffffu, a0, off);
        a1 += __shfl_down_sync(0xffffffffu, a1, off);
    }
    if (lane == 0) {
        float* dst;
        if      (stage == 0) dst = g_Dx + sb*2048;
        else if (stage == 1) dst = g_Ex + sb*2048;
        else                 dst = g_Fx + sb*2048;
        dst[w]        = a0;
        dst[1024 + w] = a1;
    }
}

// =====================================================================================
// pre kernel
// =====================================================================================
__global__ __launch_bounds__(256) void pre_kernel(const float* __restrict__ x,
                                                  const int*   __restrict__ mask,
                                                  const float* __restrict__ Wfs,
                                                  const float* __restrict__ bfs,
                                                  float* __restrict__ out, int t)
{
    const int b   = blockIdx.x >> 5;
    const int tid = threadIdx.x;
    const int nl  = tid >> 3;
    const int cg  = tid & 7;
    const int nn  = (blockIdx.x & 31) * 32 + nl;

    float s = 0.f;
    #pragma unroll
    for (int i = 0; i < 8; i++) {
        int c = cg * 8 + i;
        s += Wfs[c] * g_h[b*65536 + c*1024 + nn];
    }
    s += __shfl_down_sync(0xffffffffu, s, 4, 8);
    s += __shfl_down_sync(0xffffffffu, s, 2, 8);
    s += __shfl_down_sync(0xffffffffu, s, 1, 8);
    if (cg == 0) {
        s += bfs[0];
        out[PRED_OFF + (b*1024 + nn)*12 + t] = s;
        int m = mask[b*12288 + nn*12 + t];
        float xv = x[b*12288 + nn*12 + t];
        float x1 = m ? xv : s;
        g_z1[b*2048 + nn]        = x1;
        g_z1[b*2048 + 1024 + nn] = (float)m;
    }
}

// =====================================================================================
// decoder (16-wide n-tiles, 128 blocks)
// =====================================================================================
__global__ __launch_bounds__(256) void decoder_kernel(const float* __restrict__ bgc,
                                                      const float* __restrict__ blout,
                                                      const float* __restrict__ Wro,
                                                      const float* __restrict__ bro,
                                                      const float* __restrict__ prelu_a,
                                                      const int*   __restrict__ mask,
                                                      float* __restrict__ out, int t)
{
    const int b  = blockIdx.x >> 6;
    const int n0 = (blockIdx.x & 63) * 16;
    const int tid = threadIdx.x;
    __shared__ float E0s[64][17];
    __shared__ float E1s[64][17];
    __shared__ float Hs[64][17];
    __shared__ float Gs[64][17];
    __shared__ float Os[64][17];
    __shared__ float DXs[2][2][17];
    __shared__ float RSs[2][17];

    for (int i = tid; i < 64*16; i += 256) {
        int r = i >> 4, n = i & 15;
        E0s[r][n] = g_E64[b*65536     + r*1024 + n0 + n];
        E1s[r][n] = g_E64[(2+b)*65536 + r*1024 + n0 + n];
        Hs[r][n]  = g_h  [b*65536     + r*1024 + n0 + n];
    }
    if (tid < 64) {
        int s = tid >> 5, ch = (tid >> 4) & 1, n = tid & 15;
        DXs[s][ch][n] = g_Dx[(s*2 + b)*2048 + ch*1024 + n0 + n];
    } else if (tid < 96) {
        int idx = tid - 64; int s = idx >> 4, n = idx & 15;
        RSs[s][n] = g_rs[(s*2 + b)*1024 + n0 + n];
    }
    __syncthreads();

    const int ty = tid >> 4, tx = tid & 15;
    const int cbv = ty*4;
    float acc[4] = {};
    #pragma unroll
    for (int s = 0; s < 2; s++) {
        const float* Mt = g_M_t + s*66*64;
        {
            float4 w0 = *(const float4*)&Mt[0*64 + cbv];
            float v0 = DXs[s][0][tx];
            acc[0] += w0.x*v0; acc[1] += w0.y*v0; acc[2] += w0.z*v0; acc[3] += w0.w*v0;
            float4 w1 = *(const float4*)&Mt[1*64 + cbv];
            float v1 = DXs[s][1][tx];
            acc[0] += w1.x*v1; acc[1] += w1.y*v1; acc[2] += w1.z*v1; acc[3] += w1.w*v1;
        }
        #pragma unroll 4
        for (int k = 0; k < 64; k++) {
            float4 w = *(const float4*)&Mt[(2+k)*64 + cbv];
            float v = s ? E1s[k][tx] : E0s[k][tx];
            acc[0] += w.x*v; acc[1] += w.y*v; acc[2] += w.z*v; acc[3] += w.w*v;
        }
    }
    #pragma unroll
    for (int i = 0; i < 4; i++) {
        int c = cbv + i;
        Gs[c][tx] = acc[i] + g_vb[c]*RSs[0][tx] + g_vb[64+c]*RSs[1][tx] + bgc[c];
    }
    __syncthreads();

    float acc2[4] = {};
    #pragma unroll 4
    for (int k = 0; k < 64; k++) {
        float4 w = *(const float4*)&g_Wlout_t[k*64 + cbv];
        float v = Gs[k][tx];
        acc2[0] += w.x*v; acc2[1] += w.y*v; acc2[2] += w.z*v; acc2[3] += w.w*v;
    }
    #pragma unroll 4
    for (int k = 0; k < 64; k++) {
        float4 w = *(const float4*)&g_Wlout_t[(64+k)*64 + cbv];
        float v = Hs[k][tx];
        acc2[0] += w.x*v; acc2[1] += w.y*v; acc2[2] += w.z*v; acc2[3] += w.w*v;
    }
    const float pa = prelu_a[0];
    #pragma unroll
    for (int i = 0; i < 4; i++) {
        int c = cbv + i;
        float o = acc2[i] + blout[c]; if (o < 0.f) o *= pa;
        Os[c][tx] = o;
        g_rep[((size_t)(t*2 + b)*128 + c)*1024 + n0 + tx] = o;
    }
    __syncthreads();

    for (int i = tid; i < 64*16; i += 256) {
        int c = i >> 4, n = i & 15;
        g_rep[((size_t)(t*2 + b)*128 + 64 + c)*1024 + n0 + n] = Hs[c][n];
    }
    if (tid < 16) {
        const int n = tid, nn = n0 + n;
        float s = bro[0];
        #pragma unroll 8
        for (int c = 0; c < 64; c++) s += Wro[c]*Os[c][n] + Wro[64+c]*Hs[c][n];
        out[IMP_OFF + (b*1024 + nn)*12 + t] = s;
        int m = mask[b*12288 + nn*12 + t];
        float x2 = m ? g_z1[b*2048 + nn] : s;
        g_z2[b*2048 + nn]        = x2;
        g_z2[b*2048 + 1024 + nn] = (float)m;
    }
}

// =====================================================================================
// V330 loader (16-wide n-tile)
// =====================================================================================
__device__ __forceinline__ void load_V330_16(float (*Vs)[17], int b, int n0, int tid,
                                             const float* base64)
{
    for (int i = tid; i < 330*16; i += 256) {
        int r = i >> 4, n = i & 15;
        const float* src;
        const int sb0 = b, sb1 = 2 + b;
        if      (r < 2)   src = g_z2   + b*2048    + r*1024;
        else if (r < 66)  src = base64 + b*65536   + (r-2)*1024;
        else if (r < 68)  src = g_Ex   + sb0*2048  + (r-66)*1024;
        else if (r < 132) src = (base64 == g_h ? g_E64 : g_G64) + sb0*65536 + (r-68)*1024;
        else if (r < 134) src = g_Fx   + sb0*2048  + (r-132)*1024;
        else if (r < 198) src = (base64 == g_h ? g_F64 : g_H64) + sb0*65536 + (r-134)*1024;
        else if (r < 200) src = g_Ex   + sb1*2048  + (r-198)*1024;
        else if (r < 264) src = (base64 == g_h ? g_E64 : g_G64) + sb1*65536 + (r-200)*1024;
        else if (r < 266) src = g_Fx   + sb1*2048  + (r-264)*1024;
        else              src = (base64 == g_h ? g_F64 : g_H64) + sb1*65536 + (r-266)*1024;
        Vs[r][n] = src[n0 + n];
    }
}

__global__ __launch_bounds__(256) void gates_kernel(const float* __restrict__ br,
                                                    const float* __restrict__ bu)
{
    const int b  = blockIdx.x >> 6;
    const int n0 = (blockIdx.x & 63) * 16;
    const int tid = threadIdx.x;
    __shared__ float Vs[330][17];
    load_V330_16(Vs, b, n0, tid, g_h);
    __syncthreads();

    const int ty = tid >> 4, tx = tid & 15;
    const int cbv = ty*4;
    float ar4[4] = {}, au4[4] = {};
    #pragma unroll 5
    for (int k = 0; k < 330; k++) {
        float4 wr = *(const float4*)&g_Wr_t[k*64 + cbv];
        float4 wu = *(const float4*)&g_Wu_t[k*64 + cbv];
        float v = Vs[k][tx];
        ar4[0] += wr.x*v; ar4[1] += wr.y*v; ar4[2] += wr.z*v; ar4[3] += wr.w*v;
        au4[0] += wu.x*v; au4[1] += wu.y*v; au4[2] += wu.z*v; au4[3] += wu.w*v;
    }
    #pragma unroll
    for (int i = 0; i < 4; i++) {
        const int c = cbv + i;
        const size_t idx = (size_t)b*65536 + c*1024 + n0 + tx;
        float hv = g_h[idx];
        float r = 1.f / (1.f + expf(-(ar4[i] + br[c])));
        float u = 1.f / (1.f + expf(-(au4[i] + bu[c])));
        g_u [idx] = u;
        g_rh[idx] = r * hv;
    }
}

__global__ __launch_bounds__(256) void cand_kernel(const float* __restrict__ bc)
{
    const int b  = blockIdx.x >> 6;
    const int n0 = (blockIdx.x & 63) * 16;
    const int tid = threadIdx.x;
    __shared__ float Vs[330][17];
    load_V330_16(Vs, b, n0, tid, g_rh);
    __syncthreads();

    const int ty = tid >> 4, tx = tid & 15;
    const int cbv = ty*4;
    float acc4[4] = {};
    #pragma unroll 5
    for (int k = 0; k < 330; k++) {
        float4 w = *(const float4*)&g_Wc_t[k*64 + cbv];
        float v = Vs[k][tx];
        acc4[0] += w.x*v; acc4[1] += w.y*v; acc4[2] += w.z*v; acc4[3] += w.w*v;
    }
    #pragma unroll
    for (int i = 0; i < 4; i++) {
        const int c = cbv + i;
        const size_t idx = (size_t)b*65536 + c*1024 + n0 + tx;
        float hv = g_h[idx];
        float uv = g_u[idx];
        float cv = tanhf(acc4[i] + bc[c]);
        g_h[idx] = uv*hv + (1.f-uv)*cv;
    }
}

__global__ __launch_bounds__(256) void rep_out_kernel(float* __restrict__ out)
{
    const int bc = blockIdx.x;
    const int b = bc >> 7, cc = bc & 127;
    __shared__ float s[12][NB];
    for (int i = threadIdx.x; i < 12*NB; i += 256) {
        int t = i >> 10, n = i & 1023;
        s[t][n] = g_rep[((size_t)(t*2 + b)*128 + cc)*1024 + n];
    }
    __syncthreads();
    float* dst = out + REP_OFF + (size_t)bc * 12288;
    for (int i = threadIdx.x; i < 12288; i += 256) {
        int n = i / 12, t = i - n*12;
        dst[i] = s[t][n];
    }
}

extern "C" void kernel_launch(void* const* d_in, const int* in_sizes, int n_in,
                              void* d_out, int out_size)
{
    const float* x     = (const float*)d_in[0];
    const int*   mask  = (const int*)  d_in[1];
    const float* adj   = (const float*)d_in[2];
    const float* Wr    = (const float*)d_in[3];
    const float* br    = (const float*)d_in[4];
    const float* Wu    = (const float*)d_in[5];
    const float* bu    = (const float*)d_in[6];
    const float* Wc    = (const float*)d_in[7];
    const float* bc    = (const float*)d_in[8];
    const float* Wfs   = (const float*)d_in[9];
    const float* bfs   = (const float*)d_in[10];
    const float* Wdin  = (const float*)d_in[11];
    const float* bdin  = (const float*)d_in[12];
    const float* Wgc   = (const float*)d_in[13];
    const float* bgc   = (const float*)d_in[14];
    const float* Wlout = (const float*)d_in[15];
    const float* blout = (const float*)d_in[16];
    const float* Wro   = (const float*)d_in[17];
    const float* bro   = (const float*)d_in[18];
    const float* pa    = (const float*)d_in[19];
    float* out = (float*)d_out;

    init_h_kernel<<<512, 256>>>();
    prep_weights_kernel<<<83, 256>>>(Wr, Wu, Wc, Wlout);
    prep_M_kernel<<<dim3(17,2), 256>>>(Wgc, Wdin, bdin);
    prep_adjsplit_kernel<<<16384, 256>>>(adj);
    rowsum_kernel<<<dim3(128,4), 256>>>(adj);

    for (int t = 0; t < 12; t++) {
        pre_kernel<<<64, 256>>>(x, mask, Wfs, bfs, out, t);
        diffuse2_kernel<<<dim3(128,4), 256>>>(adj, 0);              // Dx
        diffuse_mma_kernel<<<dim3(16,4), 256>>>(0);                 // E = A h
        diffuse_mma_kernel<<<dim3(16,4), 256>>>(1);                 // F = A E
        decoder_kernel<<<128, 256>>>(bgc, blout, Wro, bro, pa, mask, out, t);
        diffuse2_kernel<<<dim3(128,4), 256>>>(adj, 1);              // Ex
        diffuse2_kernel<<<dim3(128,4), 256>>>(adj, 2);              // Fx
        gates_kernel<<<128, 256>>>(br, bu);
        diffuse_mma_kernel<<<dim3(16,4), 256>>>(2);                 // G = A rh
        diffuse_mma_kernel<<<dim3(16,4), 256>>>(3);                 // H = A G
        cand_kernel<<<128, 256>>>(bc);
    }
    rep_out_kernel<<<256, 256>>>(out);
}

// round 12
// speedup vs baseline: 1.9596x; 1.9596x over previous
#include <cuda_runtime.h>
#include <math.h>
#include <stdint.h>

// Problem: B=2, N=1024, T=12, H=64, F=1
#define NB 1024
#define IMP_OFF  0
#define PRED_OFF 24576
#define REP_OFF  49152

// ---------------- persistent scratch (device globals; no runtime allocation) ------
__device__ __align__(16) float g_h   [2*64*NB];
__device__ __align__(16) float g_E64 [4*64*NB];
__device__ __align__(16) float g_F64 [4*64*NB];
__device__ __align__(16) float g_G64 [4*64*NB];
__device__ __align__(16) float g_H64 [4*64*NB];
__device__ __align__(16) float g_Dx  [4*2*NB];
__device__ __align__(16) float g_Ex  [4*2*NB];
__device__ __align__(16) float g_Fx  [4*2*NB];
__device__ __align__(16) float g_u   [2*64*NB];
__device__ __align__(16) float g_rh  [2*64*NB];
__device__ __align__(16) float g_z1  [2*2*NB];
__device__ __align__(16) float g_z2  [2*2*NB];
__device__ __align__(16) float g_rs  [4*NB];
__device__ __align__(16) float g_rep [12*2*128*NB];
// tf32 hi/lo split of adjacency (precomputed once per replay)
__device__ __align__(16) uint32_t g_Ah[4*1024*1024];
__device__ __align__(16) uint32_t g_Al[4*1024*1024];
// transposed weights [k][c]
__device__ __align__(16) float g_Wlout_t[128*64];
__device__ __align__(16) float g_Wr_t   [330*64];
__device__ __align__(16) float g_Wu_t   [330*64];
__device__ __align__(16) float g_Wc_t   [330*64];
__device__ __align__(16) float g_M_t    [2*66*64];
__device__ __align__(16) float g_vb     [2*64];

// ---------------- helpers ----------------------------------------------------------
__device__ __forceinline__ void tf32_split1(float x, uint32_t& h, uint32_t& l) {
    asm("cvt.rna.tf32.f32 %0, %1;" : "=r"(h) : "f"(x));
    float r = x - __uint_as_float(h);
    asm("cvt.rna.tf32.f32 %0, %1;" : "=r"(l) : "f"(r));
}
#define MMA_TF32(d, a, b) \
    asm volatile("mma.sync.aligned.m16n8k8.row.col.f32.tf32.tf32.f32 " \
        "{%0,%1,%2,%3}, {%4,%5,%6,%7}, {%8,%9}, {%0,%1,%2,%3};" \
        : "+f"((d)[0]), "+f"((d)[1]), "+f"((d)[2]), "+f"((d)[3]) \
        : "r"((a)[0]), "r"((a)[1]), "r"((a)[2]), "r"((a)[3]), \
          "r"((b)[0]), "r"((b)[1]))

__global__ void init_h_kernel()
{
    int i = blockIdx.x * 256 + threadIdx.x;
    if (i < 2*64*NB) g_h[i] = 0.f;
}

__global__ void prep_adjsplit_kernel(const float* __restrict__ adj)
{
    size_t i = (size_t)blockIdx.x * 256 + threadIdx.x;
    float a = adj[i];
    uint32_t h, l;
    tf32_split1(a, h, l);
    g_Ah[i] = h;
    g_Al[i] = l;
}

__global__ void prep_weights_kernel(const float* __restrict__ Wr,
                                    const float* __restrict__ Wu,
                                    const float* __restrict__ Wc,
                                    const float* __restrict__ Wlout)
{
    int idx = blockIdx.x * 256 + threadIdx.x;
    if (idx >= 330*64) return;
    int j = idx >> 6;
    int i = idx & 63;
    g_Wr_t[idx] = Wr[i*330 + j];
    g_Wu_t[idx] = Wu[i*330 + j];
    g_Wc_t[idx] = Wc[i*330 + j];
    if (j < 128) g_Wlout_t[idx] = Wlout[i*128 + j];
}

__global__ void prep_M_kernel(const float* __restrict__ Wgc,
                              const float* __restrict__ Wdin,
                              const float* __restrict__ bdin)
{
    const int s = blockIdx.y;
    int idx = blockIdx.x * 256 + threadIdx.x;
    if (idx < 66*64) {
        int j = idx >> 6, c = idx & 63;
        float acc = 0.f;
        for (int k = 0; k < 64; k++)
            acc += Wgc[c*128 + s*64 + k] * Wdin[k*66 + j];
        g_M_t[s*66*64 + idx] = acc;
    } else if (idx < 66*64 + 64) {
        int c = idx - 66*64;
        float acc = 0.f;
        for (int k = 0; k < 64; k++)
            acc += Wgc[c*128 + s*64 + k] * bdin[k];
        g_vb[s*64 + c] = acc;
    }
}

__global__ __launch_bounds__(256) void rowsum_kernel(const float* __restrict__ adj)
{
    const int sb = blockIdx.y;
    const int warp = threadIdx.x >> 5, lane = threadIdx.x & 31;
    const int w = blockIdx.x * 8 + warp;
    const float* Arow = adj + (size_t)sb*1048576 + (size_t)w*1024;
    float a = 0.f;
    #pragma unroll
    for (int j = 0; j < 8; j++) {
        float4 av = *(const float4*)&Arow[lane*4 + j*128];
        a += av.x + av.y + av.z + av.w;
    }
    #pragma unroll
    for (int off = 16; off; off >>= 1) a += __shfl_down_sync(0xffffffffu, a, off);
    if (lane == 0) g_rs[sb*1024 + w] = a;
}

// =====================================================================================
// Tensor-pipe diffusion via mma.sync tf32 (3-term hi/lo split, ~2^-22 exact), smem-staged:
//   O[sb][c][w] = sum_v Z[c][v] * A[sb][w][v]
// CTA: M=64 x N=32, 256 thr = 8 warps (4 m-slices x 2 n-slices; warp tile M16xN16).
// K=1024 as 32 K32 tiles: LDG.128 staging -> stride-36 smem (conflict-free frag LDS).
// grid (32, 4). stage 0: h->E  1: E->F  2: rh->G  3: G->H
// =====================================================================================
#define DSTR 36
__global__ __launch_bounds__(256) void diffuse_mma_kernel(int stage)
{
    __shared__ uint32_t Zhs[64][DSTR];
    __shared__ uint32_t Zls[64][DSTR];
    __shared__ uint32_t Ahs[32][DSTR];
    __shared__ uint32_t Als[32][DSTR];

    const int sb = blockIdx.y;
    const int n0 = blockIdx.x * 32;
    const float* Z; float* O;
    switch (stage) {
        case 0:  Z = g_h   + (sb&1)*65536; O = g_E64 + sb*65536; break;
        case 1:  Z = g_E64 + sb*65536;     O = g_F64 + sb*65536; break;
        case 2:  Z = g_rh  + (sb&1)*65536; O = g_G64 + sb*65536; break;
        default: Z = g_G64 + sb*65536;     O = g_H64 + sb*65536; break;
    }
    const uint32_t* Ahp = g_Ah + (size_t)sb*1048576 + (size_t)n0*1024;
    const uint32_t* Alp = g_Al + (size_t)sb*1048576 + (size_t)n0*1024;

    const int tid  = threadIdx.x;
    const int wid  = tid >> 5, lane = tid & 31;
    // staging map
    const int zr = tid >> 2, zc = (tid & 3) * 8;   // Z: row 0..63, 8 cols
    const int ar = tid >> 3, ac = (tid & 7) * 4;   // A: row 0..31, 4 cols
    const float*    Zsrc = Z   + (size_t)zr*1024 + zc;
    const uint32_t* Ahsrc = Ahp + (size_t)ar*1024 + ac;
    const uint32_t* Alsrc = Alp + (size_t)ar*1024 + ac;
    // fragment map
    const int wy = wid >> 1, wx = wid & 1;         // m16 slice, n16 slice
    const int gid = lane >> 2, tig = lane & 3;
    const int mr0 = wy*16 + gid, mr1 = mr0 + 8;
    const int nr0 = wx*16 + gid, nr1 = nr0 + 8;

    float4 z4a, z4b; uint4 a4h, a4l;
    z4a = *(const float4*)(Zsrc);
    z4b = *(const float4*)(Zsrc + 4);
    a4h = *(const uint4*)(Ahsrc);
    a4l = *(const uint4*)(Alsrc);

    float acc[2][4] = {};   // [nt][4]

    for (int kt = 0; kt < 32; kt++) {
        // --- STS phase: split Z, store tiles ---
        uint4 zh_a, zl_a, zh_b, zl_b;
        tf32_split1(z4a.x, zh_a.x, zl_a.x); tf32_split1(z4a.y, zh_a.y, zl_a.y);
        tf32_split1(z4a.z, zh_a.z, zl_a.z); tf32_split1(z4a.w, zh_a.w, zl_a.w);
        tf32_split1(z4b.x, zh_b.x, zl_b.x); tf32_split1(z4b.y, zh_b.y, zl_b.y);
        tf32_split1(z4b.z, zh_b.z, zl_b.z); tf32_split1(z4b.w, zh_b.w, zl_b.w);
        *(uint4*)&Zhs[zr][zc]     = zh_a;
        *(uint4*)&Zhs[zr][zc + 4] = zh_b;
        *(uint4*)&Zls[zr][zc]     = zl_a;
        *(uint4*)&Zls[zr][zc + 4] = zl_b;
        *(uint4*)&Ahs[ar][ac]     = a4h;
        *(uint4*)&Als[ar][ac]     = a4l;
        __syncthreads();

        // --- prefetch next tile (overlaps MMA) ---
        if (kt < 31) {
            const int v0 = (kt + 1) * 32;
            z4a = *(const float4*)(Zsrc + v0);
            z4b = *(const float4*)(Zsrc + v0 + 4);
            a4h = *(const uint4*)(Ahsrc + v0);
            a4l = *(const uint4*)(Alsrc + v0);
        }

        // --- MMA over 4 k8 steps ---
        #pragma unroll
        for (int k8 = 0; k8 < 4; k8++) {
            const int k0 = k8 * 8;
            uint32_t zh[4], zl[4], bh0[2], bh1[2], bl0[2], bl1[2];
            zh[0] = Zhs[mr0][k0+tig];   zh[1] = Zhs[mr1][k0+tig];
            zh[2] = Zhs[mr0][k0+tig+4]; zh[3] = Zhs[mr1][k0+tig+4];
            zl[0] = Zls[mr0][k0+tig];   zl[1] = Zls[mr1][k0+tig];
            zl[2] = Zls[mr0][k0+tig+4]; zl[3] = Zls[mr1][k0+tig+4];
            bh0[0] = Ahs[nr0][k0+tig];  bh0[1] = Ahs[nr0][k0+tig+4];
            bh1[0] = Ahs[nr1][k0+tig];  bh1[1] = Ahs[nr1][k0+tig+4];
            bl0[0] = Als[nr0][k0+tig];  bl0[1] = Als[nr0][k0+tig+4];
            bl1[0] = Als[nr1][k0+tig];  bl1[1] = Als[nr1][k0+tig+4];
            MMA_TF32(acc[0], zh, bh0);
            MMA_TF32(acc[0], zh, bl0);
            MMA_TF32(acc[0], zl, bh0);
            MMA_TF32(acc[1], zh, bh1);
            MMA_TF32(acc[1], zh, bl1);
            MMA_TF32(acc[1], zl, bh1);
        }
        __syncthreads();
    }

    // epilogue: c0/c1 at (row gid, cols tig*2, tig*2+1); c2/c3 at row gid+8
    #pragma unroll
    for (int nt = 0; nt < 2; nt++) {
        const int w = n0 + wx*16 + nt*8 + tig*2;
        *(float2*)&O[(size_t)mr0*1024 + w] = make_float2(acc[nt][0], acc[nt][1]);
        *(float2*)&O[(size_t)mr1*1024 + w] = make_float2(acc[nt][2], acc[nt][3]);
    }
}

// =====================================================================================
// 2-channel diffusion. stage 0: z1->Dx  1: z2->Ex  2: Ex->Fx
// =====================================================================================
__global__ __launch_bounds__(256) void diffuse2_kernel(const float* __restrict__ adj, int stage)
{
    const int sb = blockIdx.y;
    __shared__ float zs[2][NB];
    const float* src;
    if      (stage == 0) src = g_z1 + (sb&1)*2048;
    else if (stage == 1) src = g_z2 + (sb&1)*2048;
    else                 src = g_Ex + sb*2048;
    for (int i = threadIdx.x; i < 2048; i += 256) zs[i >> 10][i & 1023] = src[i];
    __syncthreads();

    const int warp = threadIdx.x >> 5, lane = threadIdx.x & 31;
    const int w = blockIdx.x * 8 + warp;
    const float* Arow = adj + (size_t)sb*1048576 + (size_t)w*1024;
    float a0 = 0.f, a1 = 0.f;
    #pragma unroll
    for (int j = 0; j < 8; j++) {
        const int v = lane*4 + j*128;
        float4 av = *(const float4*)&Arow[v];
        float4 z0 = *(const float4*)&zs[0][v];
        float4 z1 = *(const float4*)&zs[1][v];
        a0 += av.x*z0.x + av.y*z0.y + av.z*z0.z + av.w*z0.w;
        a1 += av.x*z1.x + av.y*z1.y + av.z*z1.z + av.w*z1.w;
    }
    #pragma unroll
    for (int off = 16; off; off >>= 1) {
        a0 += __shfl_down_sync(0xffffffffu, a0, off);
        a1 += __shfl_down_sync(0xffffffffu, a1, off);
    }
    if (lane == 0) {
        float* dst;
        if      (stage == 0) dst = g_Dx + sb*2048;
        else if (stage == 1) dst = g_Ex + sb*2048;
        else                 dst = g_Fx + sb*2048;
        dst[w]        = a0;
        dst[1024 + w] = a1;
    }
}

// =====================================================================================
// pre kernel
// =====================================================================================
__global__ __launch_bounds__(256) void pre_kernel(const float* __restrict__ x,
                                                  const int*   __restrict__ mask,
                                                  const float* __restrict__ Wfs,
                                                  const float* __restrict__ bfs,
                                                  float* __restrict__ out, int t)
{
    const int b   = blockIdx.x >> 5;
    const int tid = threadIdx.x;
    const int nl  = tid >> 3;
    const int cg  = tid & 7;
    const int nn  = (blockIdx.x & 31) * 32 + nl;

    float s = 0.f;
    #pragma unroll
    for (int i = 0; i < 8; i++) {
        int c = cg * 8 + i;
        s += Wfs[c] * g_h[b*65536 + c*1024 + nn];
    }
    s += __shfl_down_sync(0xffffffffu, s, 4, 8);
    s += __shfl_down_sync(0xffffffffu, s, 2, 8);
    s += __shfl_down_sync(0xffffffffu, s, 1, 8);
    if (cg == 0) {
        s += bfs[0];
        out[PRED_OFF + (b*1024 + nn)*12 + t] = s;
        int m = mask[b*12288 + nn*12 + t];
        float xv = x[b*12288 + nn*12 + t];
        float x1 = m ? xv : s;
        g_z1[b*2048 + nn]        = x1;
        g_z1[b*2048 + 1024 + nn] = (float)m;
    }
}

// =====================================================================================
// decoder (16-wide n-tiles, 128 blocks)
// =====================================================================================
__global__ __launch_bounds__(256) void decoder_kernel(const float* __restrict__ bgc,
                                                      const float* __restrict__ blout,
                                                      const float* __restrict__ Wro,
                                                      const float* __restrict__ bro,
                                                      const float* __restrict__ prelu_a,
                                                      const int*   __restrict__ mask,
                                                      float* __restrict__ out, int t)
{
    const int b  = blockIdx.x >> 6;
    const int n0 = (blockIdx.x & 63) * 16;
    const int tid = threadIdx.x;
    __shared__ float E0s[64][17];
    __shared__ float E1s[64][17];
    __shared__ float Hs[64][17];
    __shared__ float Gs[64][17];
    __shared__ float Os[64][17];
    __shared__ float DXs[2][2][17];
    __shared__ float RSs[2][17];

    for (int i = tid; i < 64*16; i += 256) {
        int r = i >> 4, n = i & 15;
        E0s[r][n] = g_E64[b*65536     + r*1024 + n0 + n];
        E1s[r][n] = g_E64[(2+b)*65536 + r*1024 + n0 + n];
        Hs[r][n]  = g_h  [b*65536     + r*1024 + n0 + n];
    }
    if (tid < 64) {
        int s = tid >> 5, ch = (tid >> 4) & 1, n = tid & 15;
        DXs[s][ch][n] = g_Dx[(s*2 + b)*2048 + ch*1024 + n0 + n];
    } else if (tid < 96) {
        int idx = tid - 64; int s = idx >> 4, n = idx & 15;
        RSs[s][n] = g_rs[(s*2 + b)*1024 + n0 + n];
    }
    __syncthreads();

    const int ty = tid >> 4, tx = tid & 15;
    const int cbv = ty*4;
    float acc[4] = {};
    #pragma unroll
    for (int s = 0; s < 2; s++) {
        const float* Mt = g_M_t + s*66*64;
        {
            float4 w0 = *(const float4*)&Mt[0*64 + cbv];
            float v0 = DXs[s][0][tx];
            acc[0] += w0.x*v0; acc[1] += w0.y*v0; acc[2] += w0.z*v0; acc[3] += w0.w*v0;
            float4 w1 = *(const float4*)&Mt[1*64 + cbv];
            float v1 = DXs[s][1][tx];
            acc[0] += w1.x*v1; acc[1] += w1.y*v1; acc[2] += w1.z*v1; acc[3] += w1.w*v1;
        }
        #pragma unroll 4
        for (int k = 0; k < 64; k++) {
            float4 w = *(const float4*)&Mt[(2+k)*64 + cbv];
            float v = s ? E1s[k][tx] : E0s[k][tx];
            acc[0] += w.x*v; acc[1] += w.y*v; acc[2] += w.z*v; acc[3] += w.w*v;
        }
    }
    #pragma unroll
    for (int i = 0; i < 4; i++) {
        int c = cbv + i;
        Gs[c][tx] = acc[i] + g_vb[c]*RSs[0][tx] + g_vb[64+c]*RSs[1][tx] + bgc[c];
    }
    __syncthreads();

    float acc2[4] = {};
    #pragma unroll 4
    for (int k = 0; k < 64; k++) {
        float4 w = *(const float4*)&g_Wlout_t[k*64 + cbv];
        float v = Gs[k][tx];
        acc2[0] += w.x*v; acc2[1] += w.y*v; acc2[2] += w.z*v; acc2[3] += w.w*v;
    }
    #pragma unroll 4
    for (int k = 0; k < 64; k++) {
        float4 w = *(const float4*)&g_Wlout_t[(64+k)*64 + cbv];
        float v = Hs[k][tx];
        acc2[0] += w.x*v; acc2[1] += w.y*v; acc2[2] += w.z*v; acc2[3] += w.w*v;
    }
    const float pa = prelu_a[0];
    #pragma unroll
    for (int i = 0; i < 4; i++) {
        int c = cbv + i;
        float o = acc2[i] + blout[c]; if (o < 0.f) o *= pa;
        Os[c][tx] = o;
        g_rep[((size_t)(t*2 + b)*128 + c)*1024 + n0 + tx] = o;
    }
    __syncthreads();

    for (int i = tid; i < 64*16; i += 256) {
        int c = i >> 4, n = i & 15;
        g_rep[((size_t)(t*2 + b)*128 + 64 + c)*1024 + n0 + n] = Hs[c][n];
    }
    if (tid < 16) {
        const int n = tid, nn = n0 + n;
        float s = bro[0];
        #pragma unroll 8
        for (int c = 0; c < 64; c++) s += Wro[c]*Os[c][n] + Wro[64+c]*Hs[c][n];
        out[IMP_OFF + (b*1024 + nn)*12 + t] = s;
        int m = mask[b*12288 + nn*12 + t];
        float x2 = m ? g_z1[b*2048 + nn] : s;
        g_z2[b*2048 + nn]        = x2;
        g_z2[b*2048 + 1024 + nn] = (float)m;
    }
}

// =====================================================================================
// V330 loader (16-wide n-tile)
// =====================================================================================
__device__ __forceinline__ void load_V330_16(float (*Vs)[17], int b, int n0, int tid,
                                             const float* base64)
{
    for (int i = tid; i < 330*16; i += 256) {
        int r = i >> 4, n = i & 15;
        const float* src;
        const int sb0 = b, sb1 = 2 + b;
        if      (r < 2)   src = g_z2   + b*2048    + r*1024;
        else if (r < 66)  src = base64 + b*65536   + (r-2)*1024;
        else if (r < 68)  src = g_Ex   + sb0*2048  + (r-66)*1024;
        else if (r < 132) src = (base64 == g_h ? g_E64 : g_G64) + sb0*65536 + (r-68)*1024;
        else if (r < 134) src = g_Fx   + sb0*2048  + (r-132)*1024;
        else if (r < 198) src = (base64 == g_h ? g_F64 : g_H64) + sb0*65536 + (r-134)*1024;
        else if (r < 200) src = g_Ex   + sb1*2048  + (r-198)*1024;
        else if (r < 264) src = (base64 == g_h ? g_E64 : g_G64) + sb1*65536 + (r-200)*1024;
        else if (r < 266) src = g_Fx   + sb1*2048  + (r-264)*1024;
        else              src = (base64 == g_h ? g_F64 : g_H64) + sb1*65536 + (r-266)*1024;
        Vs[r][n] = src[n0 + n];
    }
}

__global__ __launch_bounds__(256) void gates_kernel(const float* __restrict__ br,
                                                    const float* __restrict__ bu)
{
    const int b  = blockIdx.x >> 6;
    const int n0 = (blockIdx.x & 63) * 16;
    const int tid = threadIdx.x;
    __shared__ float Vs[330][17];
    load_V330_16(Vs, b, n0, tid, g_h);
    __syncthreads();

    const int ty = tid >> 4, tx = tid & 15;
    const int cbv = ty*4;
    float ar4[4] = {}, au4[4] = {};
    #pragma unroll 5
    for (int k = 0; k < 330; k++) {
        float4 wr = *(const float4*)&g_Wr_t[k*64 + cbv];
        float4 wu = *(const float4*)&g_Wu_t[k*64 + cbv];
        float v = Vs[k][tx];
        ar4[0] += wr.x*v; ar4[1] += wr.y*v; ar4[2] += wr.z*v; ar4[3] += wr.w*v;
        au4[0] += wu.x*v; au4[1] += wu.y*v; au4[2] += wu.z*v; au4[3] += wu.w*v;
    }
    #pragma unroll
    for (int i = 0; i < 4; i++) {
        const int c = cbv + i;
        const size_t idx = (size_t)b*65536 + c*1024 + n0 + tx;
        float hv = g_h[idx];
        float r = 1.f / (1.f + expf(-(ar4[i] + br[c])));
        float u = 1.f / (1.f + expf(-(au4[i] + bu[c])));
        g_u [idx] = u;
        g_rh[idx] = r * hv;
    }
}

__global__ __launch_bounds__(256) void cand_kernel(const float* __restrict__ bc)
{
    const int b  = blockIdx.x >> 6;
    const int n0 = (blockIdx.x & 63) * 16;
    const int tid = threadIdx.x;
    __shared__ float Vs[330][17];
    load_V330_16(Vs, b, n0, tid, g_rh);
    __syncthreads();

    const int ty = tid >> 4, tx = tid & 15;
    const int cbv = ty*4;
    float acc4[4] = {};
    #pragma unroll 5
    for (int k = 0; k < 330; k++) {
        float4 w = *(const float4*)&g_Wc_t[k*64 + cbv];
        float v = Vs[k][tx];
        acc4[0] += w.x*v; acc4[1] += w.y*v; acc4[2] += w.z*v; acc4[3] += w.w*v;
    }
    #pragma unroll
    for (int i = 0; i < 4; i++) {
        const int c = cbv + i;
        const size_t idx = (size_t)b*65536 + c*1024 + n0 + tx;
        float hv = g_h[idx];
        float uv = g_u[idx];
        float cv = tanhf(acc4[i] + bc[c]);
        g_h[idx] = uv*hv + (1.f-uv)*cv;
    }
}

__global__ __launch_bounds__(256) void rep_out_kernel(float* __restrict__ out)
{
    const int bc = blockIdx.x;
    const int b = bc >> 7, cc = bc & 127;
    __shared__ float s[12][NB];
    for (int i = threadIdx.x; i < 12*NB; i += 256) {
        int t = i >> 10, n = i & 1023;
        s[t][n] = g_rep[((size_t)(t*2 + b)*128 + cc)*1024 + n];
    }
    __syncthreads();
    float* dst = out + REP_OFF + (size_t)bc * 12288;
    for (int i = threadIdx.x; i < 12288; i += 256) {
        int n = i / 12, t = i - n*12;
        dst[i] = s[t][n];
    }
}

extern "C" void kernel_launch(void* const* d_in, const int* in_sizes, int n_in,
                              void* d_out, int out_size)
{
    const float* x     = (const float*)d_in[0];
    const int*   mask  = (const int*)  d_in[1];
    const float* adj   = (const float*)d_in[2];
    const float* Wr    = (const float*)d_in[3];
    const float* br    = (const float*)d_in[4];
    const float* Wu    = (const float*)d_in[5];
    const float* bu    = (const float*)d_in[6];
    const float* Wc    = (const float*)d_in[7];
    const float* bc    = (const float*)d_in[8];
    const float* Wfs   = (const float*)d_in[9];
    const float* bfs   = (const float*)d_in[10];
    const float* Wdin  = (const float*)d_in[11];
    const float* bdin  = (const float*)d_in[12];
    const float* Wgc   = (const float*)d_in[13];
    const float* bgc   = (const float*)d_in[14];
    const float* Wlout = (const float*)d_in[15];
    const float* blout = (const float*)d_in[16];
    const float* Wro   = (const float*)d_in[17];
    const float* bro   = (const float*)d_in[18];
    const float* pa    = (const float*)d_in[19];
    float* out = (float*)d_out;

    init_h_kernel<<<512, 256>>>();
    prep_weights_kernel<<<83, 256>>>(Wr, Wu, Wc, Wlout);
    prep_M_kernel<<<dim3(17,2), 256>>>(Wgc, Wdin, bdin);
    prep_adjsplit_kernel<<<16384, 256>>>(adj);
    rowsum_kernel<<<dim3(128,4), 256>>>(adj);

    for (int t = 0; t < 12; t++) {
        pre_kernel<<<64, 256>>>(x, mask, Wfs, bfs, out, t);
        diffuse2_kernel<<<dim3(128,4), 256>>>(adj, 0);              // Dx
        diffuse_mma_kernel<<<dim3(32,4), 256>>>(0);                 // E = A h
        diffuse_mma_kernel<<<dim3(32,4), 256>>>(1);                 // F = A E
        decoder_kernel<<<128, 256>>>(bgc, blout, Wro, bro, pa, mask, out, t);
        diffuse2_kernel<<<dim3(128,4), 256>>>(adj, 1);              // Ex
        diffuse2_kernel<<<dim3(128,4), 256>>>(adj, 2);              // Fx
        gates_kernel<<<128, 256>>>(br, bu);
        diffuse_mma_kernel<<<dim3(32,4), 256>>>(2);                 // G = A rh
        diffuse_mma_kernel<<<dim3(32,4), 256>>>(3);                 // H = A G
        cand_kernel<<<128, 256>>>(bc);
    }
    rep_out_kernel<<<256, 256>>>(out);
}